// round 11
// baseline (speedup 1.0000x reference)
#include <cuda_runtime.h>
#include <cuda_bf16.h>
#include <cstdint>

// FactoredQuantizer: B=8192, M=16, N=256, C=64
// R10: register-path tensor cores (mma.sync m16n8k16 bf16, sm_80-era — compiles
// on plain sm_103 unlike tcgen05). Exact bf16 hi/lo 3-term split with fp32
// accumulate; argmin gap-test (TAU) + exact-fp32 refine keeps rel_err = 0.

#define BQ 8192
#define MQ 16
#define NQ 256
#define CQ 64
#define QT 128
#define NTHREADS 256
#define TAU 0.0625f
#define FLT_BIG 3.402823466e38f

#define SW128(bo) ((bo) ^ (((bo) >> 3) & 0x70))

// smem layout (all tiles 1024-aligned; bf16 rows = 128 B, SW128 swizzle)
#define SM_A_HI 0            // [128][64] bf16 = 16 KB
#define SM_A_LO 16384
#define SM_B_HI 32768        // [256][64] bf16 = 32 KB
#define SM_B_LO 65536
#define SM_C2   98304        // 256 f32
#define SM_WIN  99328        // 128 int
#define SM_TOTAL 99840

__device__ __forceinline__ uint32_t smem_u32(const void* p) {
    uint32_t a;
    asm("{ .reg .u64 t; cvta.to.shared.u64 t, %1; cvt.u32.u64 %0, t; }"
        : "=r"(a) : "l"(p));
    return a;
}

__device__ __forceinline__ void ldmx4(uint32_t* r, uint32_t addr) {
    asm volatile("ldmatrix.sync.aligned.m8n8.x4.shared.b16 {%0,%1,%2,%3}, [%4];"
                 : "=r"(r[0]), "=r"(r[1]), "=r"(r[2]), "=r"(r[3]) : "r"(addr));
}

__device__ __forceinline__ void mma_bf16(float* c, const uint32_t* a,
                                         uint32_t b0, uint32_t b1) {
    asm volatile(
        "mma.sync.aligned.m16n8k16.row.col.f32.bf16.bf16.f32 "
        "{%0,%1,%2,%3}, {%4,%5,%6,%7}, {%8,%9}, {%0,%1,%2,%3};"
        : "+f"(c[0]), "+f"(c[1]), "+f"(c[2]), "+f"(c[3])
        : "r"(a[0]), "r"(a[1]), "r"(a[2]), "r"(a[3]), "r"(b0), "r"(b1));
}

// split fp32 pair -> bf16 hi/lo, store u32 (2 bf16) at swizzled offset
__device__ __forceinline__ void cvt_store_pair(char* hi_base, char* lo_base,
                                               uint32_t bo, float a, float b) {
    __nv_bfloat16 ha = __float2bfloat16(a), hb = __float2bfloat16(b);
    float la = a - __bfloat162float(ha);
    float lb = b - __bfloat162float(hb);
    __nv_bfloat16 lha = __float2bfloat16(la), lhb = __float2bfloat16(lb);
    uint32_t hw = (uint32_t)__bfloat16_as_ushort(ha)
                | ((uint32_t)__bfloat16_as_ushort(hb) << 16);
    uint32_t lw = (uint32_t)__bfloat16_as_ushort(lha)
                | ((uint32_t)__bfloat16_as_ushort(lhb) << 16);
    uint32_t so = SW128(bo);
    *(uint32_t*)(hi_base + so) = hw;
    *(uint32_t*)(lo_base + so) = lw;
}

// exact fp32 distance, sequential fmaf (matches c2 construction order)
__device__ __forceinline__ float exact_dist(const float* __restrict__ xr,
                                            const float* __restrict__ cr,
                                            float c2n) {
    float s = 0.f;
    #pragma unroll 8
    for (int k = 0; k < CQ; k++) s = fmaf(xr[k], cr[k], s);
    return fmaf(-2.0f, s, c2n);
}

__global__ __launch_bounds__(NTHREADS, 2)
void fq_mma_kernel(const float* __restrict__ x,
                   const float* __restrict__ cb,
                   float* __restrict__ out_codes,
                   float* __restrict__ out_idx) {
    extern __shared__ char smem[];
    const uint32_t sb = smem_u32(smem);
    float* s_c2  = (float*)(smem + SM_C2);
    int*   s_win = (int*)  (smem + SM_WIN);

    const int t = threadIdx.x, wid = t >> 5, lane = t & 31;
    const int m = blockIdx.y;
    const int qbase = blockIdx.x * QT;
    const float* gcb = cb + (size_t)m * NQ * CQ;

    // ---- stage A = x tile [128][64]: f32 -> bf16 hi/lo, SW128 ----
    #pragma unroll
    for (int i = 0; i < 8; i++) {
        int idx = t + NTHREADS * i;            // 0..2047 float4s
        int row = idx >> 4, c4 = idx & 15;
        float4 v = *(const float4*)(x + ((size_t)(qbase + row) * MQ + m) * CQ + c4 * 4);
        uint32_t bo = row * 128 + c4 * 8;
        cvt_store_pair(smem + SM_A_HI, smem + SM_A_LO, bo,     v.x, v.y);
        cvt_store_pair(smem + SM_A_HI, smem + SM_A_LO, bo + 4, v.z, v.w);
    }
    // ---- stage B = codebook[m] [256][64] ----
    #pragma unroll
    for (int i = 0; i < 16; i++) {
        int idx = t + NTHREADS * i;            // 0..4095 float4s
        int row = idx >> 4, c4 = idx & 15;
        float4 v = ((const float4*)gcb)[idx];
        uint32_t bo = row * 128 + c4 * 8;
        cvt_store_pair(smem + SM_B_HI, smem + SM_B_LO, bo,     v.x, v.y);
        cvt_store_pair(smem + SM_B_HI, smem + SM_B_LO, bo + 4, v.z, v.w);
    }
    // ---- c2[n]: thread t owns row t, sequential fmaf (deterministic) ----
    {
        float s = 0.f;
        const float* r = gcb + t * CQ;
        #pragma unroll 8
        for (int k = 0; k < CQ; k++) s = fmaf(r[k], r[k], s);
        s_c2[t] = s;
    }
    __syncthreads();

    // ---- A fragments (register-resident, reused over all N) ----
    const int m0 = wid * 16;                   // warp's 16 query rows
    const int lg = lane >> 3, li = lane & 7;
    // A ldmatrix.x4 matrix order: (m0,k0) (m0+8,k0) (m0,k8) (m0+8,k8)
    const int arow  = m0 + li + ((lg & 1) ? 8 : 0);
    const int akoff = (lg >= 2) ? 16 : 0;
    uint32_t a_hi[16], a_lo[16];
    #pragma unroll
    for (int ks = 0; ks < 4; ks++) {
        uint32_t bo = arow * 128 + ks * 32 + akoff;
        ldmx4(a_hi + ks * 4, sb + SM_A_HI + SW128(bo));
        ldmx4(a_lo + ks * 4, sb + SM_A_LO + SW128(bo));
    }

    // B ldmatrix.x4 matrix order: (n0,k0) (n0,k8) (n0+8,k0) (n0+8,k8)
    const int brow_off = li + ((lg >= 2) ? 8 : 0);
    const int bkoff    = (lg & 1) ? 16 : 0;

    // ---- mainloop over 16 n-pairs (16 codes each) ----
    float bv1[2] = {FLT_BIG, FLT_BIG}, bv2[2] = {FLT_BIG, FLT_BIG};
    int   bi1[2] = {0, 0};
    const int r2 = (lane & 3) * 2;

    for (int np = 0; np < 16; np++) {
        float acch[8], accr[8];
        #pragma unroll
        for (int i = 0; i < 8; i++) { acch[i] = 0.f; accr[i] = 0.f; }

        #pragma unroll
        for (int ks = 0; ks < 4; ks++) {
            uint32_t bh[4], bl[4];
            uint32_t bo = (np * 16 + brow_off) * 128 + ks * 32 + bkoff;
            ldmx4(bh, sb + SM_B_HI + SW128(bo));
            ldmx4(bl, sb + SM_B_LO + SW128(bo));
            mma_bf16(acch + 0, a_hi + ks * 4, bh[0], bh[1]);   // hi*hi, ntile0
            mma_bf16(acch + 4, a_hi + ks * 4, bh[2], bh[3]);   // hi*hi, ntile1
            mma_bf16(accr + 0, a_lo + ks * 4, bh[0], bh[1]);   // lo*hi
            mma_bf16(accr + 4, a_lo + ks * 4, bh[2], bh[3]);
            mma_bf16(accr + 0, a_hi + ks * 4, bl[0], bl[1]);   // hi*lo
            mma_bf16(accr + 4, a_hi + ks * 4, bl[2], bl[3]);
        }

        // epilogue: per lane 8 dots; rows m0+lane/4 (r=0) and +8 (r=1)
        const int nb = np * 16;
        float c2a = s_c2[nb + r2],     c2b = s_c2[nb + r2 + 1];
        float c2c = s_c2[nb + 8 + r2], c2d = s_c2[nb + 8 + r2 + 1];
        #pragma unroll
        for (int r = 0; r < 2; r++) {
            float d0 = fmaf(-2.f, acch[2*r + 0] + accr[2*r + 0], c2a);
            float d1 = fmaf(-2.f, acch[2*r + 1] + accr[2*r + 1], c2b);
            float d2 = fmaf(-2.f, acch[2*r + 4] + accr[2*r + 4], c2c);
            float d3 = fmaf(-2.f, acch[2*r + 5] + accr[2*r + 5], c2d);
            float v1 = bv1[r], v2 = bv2[r]; int i1 = bi1[r];
            if (d0 < v1) { v2 = v1; v1 = d0; i1 = nb + r2; }     else if (d0 < v2) v2 = d0;
            if (d1 < v1) { v2 = v1; v1 = d1; i1 = nb + r2 + 1; } else if (d1 < v2) v2 = d1;
            if (d2 < v1) { v2 = v1; v1 = d2; i1 = nb + 8 + r2; } else if (d2 < v2) v2 = d2;
            if (d3 < v1) { v2 = v1; v1 = d3; i1 = nb + 8 + r2 + 1; } else if (d3 < v2) v2 = d3;
            bv1[r] = v1; bv2[r] = v2; bi1[r] = i1;
        }
    }

    // ---- per-row quad reduce + gap test + exact refine ----
    const unsigned quadmask = 0xFu << (lane & ~3u);
    #pragma unroll
    for (int r = 0; r < 2; r++) {
        const int qrow = m0 + (lane >> 2) + 8 * r;     // row index in block
        float v1 = bv1[r], v2 = bv2[r]; int i1 = bi1[r];

        float gm1 = v1, gm2 = v2; int gi1 = i1;
        #pragma unroll
        for (int off = 1; off <= 2; off <<= 1) {
            float o1 = __shfl_xor_sync(0xffffffff, gm1, off);
            int   oi = __shfl_xor_sync(0xffffffff, gi1, off);
            float o2 = __shfl_xor_sync(0xffffffff, gm2, off);
            if (o1 < gm1 || (o1 == gm1 && oi < gi1)) {
                gm2 = fminf(gm1, o2); gm1 = o1; gi1 = oi;
            } else {
                gm2 = fminf(gm2, o1);
            }
        }

        int winner = gi1;
        if (gm2 - gm1 < TAU) {                         // quad-uniform condition
            const float th = gm1 + TAU;
            float ev = FLT_BIG; int ei = 0x7fffffff;
            const float* xr = x + ((size_t)(qbase + qrow) * MQ + m) * CQ;
            if (v2 < th) {
                // fallback: exact scan of ALL 64 n's this lane owns (rare)
                for (int np = 0; np < 16; np++) {
                    int nn[4] = { np*16 + r2, np*16 + r2 + 1,
                                  np*16 + 8 + r2, np*16 + 8 + r2 + 1 };
                    #pragma unroll
                    for (int j = 0; j < 4; j++) {
                        float d = exact_dist(xr, gcb + nn[j] * CQ, s_c2[nn[j]]);
                        if (d < ev || (d == ev && nn[j] < ei)) { ev = d; ei = nn[j]; }
                    }
                }
            } else if (v1 < th) {
                ev = exact_dist(xr, gcb + i1 * CQ, s_c2[i1]);
                ei = i1;
            }
            #pragma unroll
            for (int off = 1; off <= 2; off <<= 1) {
                float oe = __shfl_xor_sync(quadmask, ev, off);
                int   oi = __shfl_xor_sync(quadmask, ei, off);
                if (oe < ev || (oe == ev && oi < ei)) { ev = oe; ei = oi; }
            }
            winner = ei;
        }
        if ((lane & 3) == 0) s_win[qrow] = winner;
    }
    __syncwarp();   // s_win rows for this warp written/read by this warp only

    // ---- output: warp copies its 16 query rows (codebook L2-hot) ----
    #pragma unroll
    for (int i = 0; i < 16; i++) {
        int q = wid * 16 + i;
        int n = s_win[q];
        size_t orow = ((size_t)(qbase + q) * MQ + m) * CQ;
        const float2* src = (const float2*)(gcb + (size_t)n * CQ);
        ((float2*)(out_codes + orow))[lane] = src[lane];
        if (lane == 0 && out_idx)
            out_idx[(size_t)(qbase + q) * MQ + m] = (float)n;
    }
}

extern "C" void kernel_launch(void* const* d_in, const int* in_sizes, int n_in,
                              void* d_out, int out_size) {
    const float* x  = (const float*)d_in[0];
    const float* cb = (const float*)d_in[1];
    if (n_in >= 2 && in_sizes[0] == MQ * NQ * CQ) {
        const float* tmp = x; x = cb; cb = tmp;
    }

    float* out_codes = (float*)d_out;
    float* out_idx   = nullptr;
    const long long codes_elems = (long long)BQ * MQ * CQ;   // 8388608
    if ((long long)out_size >= codes_elems + (long long)BQ * MQ)
        out_idx = out_codes + codes_elems;

    cudaFuncSetAttribute(fq_mma_kernel, cudaFuncAttributeMaxDynamicSharedMemorySize,
                         SM_TOTAL);
    dim3 grid(BQ / QT, MQ);   // 64 x 16 = 1024 CTAs
    fq_mma_kernel<<<grid, NTHREADS, SM_TOTAL>>>(x, cb, out_codes, out_idx);
}

// round 13
// speedup vs baseline: 1.4233x; 1.4233x over previous
#include <cuda_runtime.h>
#include <cuda_bf16.h>
#include <cstdint>

// FactoredQuantizer: B=8192, M=16, N=256, C=64
// R11: mma.sync bf16 3-term split (verified exact in R10) with 2 m-tiles per
// warp (256-query CTA tile) -> 12 independent MMAs per B load, 8 independent
// accumulator chains: hides latency at low occupancy. TAU gap-test + exact
// fp32 refine keeps rel_err = 0.

#define BQ 8192
#define MQ 16
#define NQ 256
#define CQ 64
#define QT 256
#define NTHREADS 256
#define TAU 0.0625f
#define FLT_BIG 3.402823466e38f

#define SW128(bo) ((bo) ^ (((bo) >> 3) & 0x70))

// smem layout (bf16 rows = 128 B, SW128 swizzle)
#define SM_A_HI 0            // [256][64] bf16 = 32 KB
#define SM_A_LO 32768
#define SM_B_HI 65536        // [256][64] bf16 = 32 KB
#define SM_B_LO 98304
#define SM_C2   131072       // 256 f32
#define SM_WIN  132096       // 256 int
#define SM_TOTAL 133120

__device__ __forceinline__ uint32_t smem_u32(const void* p) {
    uint32_t a;
    asm("{ .reg .u64 t; cvta.to.shared.u64 t, %1; cvt.u32.u64 %0, t; }"
        : "=r"(a) : "l"(p));
    return a;
}

__device__ __forceinline__ void ldmx4(uint32_t* r, uint32_t addr) {
    asm volatile("ldmatrix.sync.aligned.m8n8.x4.shared.b16 {%0,%1,%2,%3}, [%4];"
                 : "=r"(r[0]), "=r"(r[1]), "=r"(r[2]), "=r"(r[3]) : "r"(addr));
}

__device__ __forceinline__ void mma_bf16(float* c, const uint32_t* a,
                                         uint32_t b0, uint32_t b1) {
    asm volatile(
        "mma.sync.aligned.m16n8k16.row.col.f32.bf16.bf16.f32 "
        "{%0,%1,%2,%3}, {%4,%5,%6,%7}, {%8,%9}, {%0,%1,%2,%3};"
        : "+f"(c[0]), "+f"(c[1]), "+f"(c[2]), "+f"(c[3])
        : "r"(a[0]), "r"(a[1]), "r"(a[2]), "r"(a[3]), "r"(b0), "r"(b1));
}

__device__ __forceinline__ void cvt_store_pair(char* hi_base, char* lo_base,
                                               uint32_t bo, float a, float b) {
    __nv_bfloat16 ha = __float2bfloat16(a), hb = __float2bfloat16(b);
    float la = a - __bfloat162float(ha);
    float lb = b - __bfloat162float(hb);
    __nv_bfloat16 lha = __float2bfloat16(la), lhb = __float2bfloat16(lb);
    uint32_t hw = (uint32_t)__bfloat16_as_ushort(ha)
                | ((uint32_t)__bfloat16_as_ushort(hb) << 16);
    uint32_t lw = (uint32_t)__bfloat16_as_ushort(lha)
                | ((uint32_t)__bfloat16_as_ushort(lhb) << 16);
    uint32_t so = SW128(bo);
    *(uint32_t*)(hi_base + so) = hw;
    *(uint32_t*)(lo_base + so) = lw;
}

__device__ __forceinline__ float exact_dist(const float* __restrict__ xr,
                                            const float* __restrict__ cr,
                                            float c2n) {
    float s = 0.f;
    #pragma unroll 8
    for (int k = 0; k < CQ; k++) s = fmaf(xr[k], cr[k], s);
    return fmaf(-2.0f, s, c2n);
}

__global__ __launch_bounds__(NTHREADS, 1)
void fq_mma_kernel(const float* __restrict__ x,
                   const float* __restrict__ cb,
                   float* __restrict__ out_codes,
                   float* __restrict__ out_idx) {
    extern __shared__ char smem[];
    const uint32_t sb = smem_u32(smem);
    float* s_c2  = (float*)(smem + SM_C2);
    int*   s_win = (int*)  (smem + SM_WIN);

    const int t = threadIdx.x, wid = t >> 5, lane = t & 31;
    const int m = blockIdx.y;
    const int qbase = blockIdx.x * QT;
    const float* gcb = cb + (size_t)m * NQ * CQ;

    // ---- stage A = x tile [256][64]: f32 -> bf16 hi/lo, SW128 ----
    #pragma unroll
    for (int i = 0; i < 16; i++) {
        int idx = t + NTHREADS * i;            // 0..4095 float4s
        int row = idx >> 4, c4 = idx & 15;
        float4 v = *(const float4*)(x + ((size_t)(qbase + row) * MQ + m) * CQ + c4 * 4);
        uint32_t bo = row * 128 + c4 * 8;
        cvt_store_pair(smem + SM_A_HI, smem + SM_A_LO, bo,     v.x, v.y);
        cvt_store_pair(smem + SM_A_HI, smem + SM_A_LO, bo + 4, v.z, v.w);
    }
    // ---- stage B = codebook[m] [256][64] ----
    #pragma unroll
    for (int i = 0; i < 16; i++) {
        int idx = t + NTHREADS * i;
        int row = idx >> 4, c4 = idx & 15;
        float4 v = ((const float4*)gcb)[idx];
        uint32_t bo = row * 128 + c4 * 8;
        cvt_store_pair(smem + SM_B_HI, smem + SM_B_LO, bo,     v.x, v.y);
        cvt_store_pair(smem + SM_B_HI, smem + SM_B_LO, bo + 4, v.z, v.w);
    }
    // ---- c2[n]: thread t owns row t, sequential fmaf ----
    {
        float s = 0.f;
        const float* r = gcb + t * CQ;
        #pragma unroll 8
        for (int k = 0; k < CQ; k++) s = fmaf(r[k], r[k], s);
        s_c2[t] = s;
    }
    __syncthreads();

    // ---- A fragments: TWO m16 tiles per warp (rows wid*16, 128+wid*16) ----
    const int m0 = wid * 16;
    const int lg = lane >> 3, li = lane & 7;
    const int arow_in = li + ((lg & 1) ? 8 : 0);
    const int akoff   = (lg >= 2) ? 16 : 0;
    uint32_t a_hi[2][16], a_lo[2][16];
    #pragma unroll
    for (int mt = 0; mt < 2; mt++) {
        const int arow = mt * 128 + m0 + arow_in;
        #pragma unroll
        for (int ks = 0; ks < 4; ks++) {
            uint32_t bo = arow * 128 + ks * 32 + akoff;
            ldmx4(a_hi[mt] + ks * 4, sb + SM_A_HI + SW128(bo));
            ldmx4(a_lo[mt] + ks * 4, sb + SM_A_LO + SW128(bo));
        }
    }

    const int brow_off = li + ((lg >= 2) ? 8 : 0);
    const int bkoff    = (lg & 1) ? 16 : 0;
    const int r2 = (lane & 3) * 2;

    float bv1[2][2], bv2[2][2];
    int   bi1[2][2];
    #pragma unroll
    for (int mt = 0; mt < 2; mt++)
        #pragma unroll
        for (int r = 0; r < 2; r++) {
            bv1[mt][r] = FLT_BIG; bv2[mt][r] = FLT_BIG; bi1[mt][r] = 0;
        }

    // ---- mainloop: 16 n-pair groups; 12 MMAs per B load, 8 acc chains ----
    #pragma unroll 2
    for (int np = 0; np < 16; np++) {
        float acch[2][8], accr[2][8];
        #pragma unroll
        for (int mt = 0; mt < 2; mt++)
            #pragma unroll
            for (int i = 0; i < 8; i++) { acch[mt][i] = 0.f; accr[mt][i] = 0.f; }

        #pragma unroll
        for (int ks = 0; ks < 4; ks++) {
            uint32_t bh[4], bl[4];
            uint32_t bo = (np * 16 + brow_off) * 128 + ks * 32 + bkoff;
            ldmx4(bh, sb + SM_B_HI + SW128(bo));
            ldmx4(bl, sb + SM_B_LO + SW128(bo));
            #pragma unroll
            for (int mt = 0; mt < 2; mt++) {
                mma_bf16(acch[mt] + 0, a_hi[mt] + ks * 4, bh[0], bh[1]);
                mma_bf16(acch[mt] + 4, a_hi[mt] + ks * 4, bh[2], bh[3]);
                mma_bf16(accr[mt] + 0, a_lo[mt] + ks * 4, bh[0], bh[1]);
                mma_bf16(accr[mt] + 4, a_lo[mt] + ks * 4, bh[2], bh[3]);
                mma_bf16(accr[mt] + 0, a_hi[mt] + ks * 4, bl[0], bl[1]);
                mma_bf16(accr[mt] + 4, a_hi[mt] + ks * 4, bl[2], bl[3]);
            }
        }

        const int nb = np * 16;
        float c2a = s_c2[nb + r2],     c2b = s_c2[nb + r2 + 1];
        float c2c = s_c2[nb + 8 + r2], c2d = s_c2[nb + 8 + r2 + 1];
        #pragma unroll
        for (int mt = 0; mt < 2; mt++) {
            #pragma unroll
            for (int r = 0; r < 2; r++) {
                float d0 = fmaf(-2.f, acch[mt][2*r + 0] + accr[mt][2*r + 0], c2a);
                float d1 = fmaf(-2.f, acch[mt][2*r + 1] + accr[mt][2*r + 1], c2b);
                float d2 = fmaf(-2.f, acch[mt][2*r + 4] + accr[mt][2*r + 4], c2c);
                float d3 = fmaf(-2.f, acch[mt][2*r + 5] + accr[mt][2*r + 5], c2d);
                float v1 = bv1[mt][r], v2 = bv2[mt][r]; int i1 = bi1[mt][r];
                if (d0 < v1) { v2 = v1; v1 = d0; i1 = nb + r2; }     else if (d0 < v2) v2 = d0;
                if (d1 < v1) { v2 = v1; v1 = d1; i1 = nb + r2 + 1; } else if (d1 < v2) v2 = d1;
                if (d2 < v1) { v2 = v1; v1 = d2; i1 = nb + 8 + r2; } else if (d2 < v2) v2 = d2;
                if (d3 < v1) { v2 = v1; v1 = d3; i1 = nb + 8 + r2 + 1; } else if (d3 < v2) v2 = d3;
                bv1[mt][r] = v1; bv2[mt][r] = v2; bi1[mt][r] = i1;
            }
        }
    }

    // ---- per-row quad reduce + gap test + exact refine ----
    const unsigned quadmask = 0xFu << (lane & ~3u);
    #pragma unroll
    for (int mt = 0; mt < 2; mt++) {
        #pragma unroll
        for (int r = 0; r < 2; r++) {
            const int qrow = mt * 128 + m0 + (lane >> 2) + 8 * r;
            float v1 = bv1[mt][r], v2 = bv2[mt][r]; int i1 = bi1[mt][r];

            float gm1 = v1, gm2 = v2; int gi1 = i1;
            #pragma unroll
            for (int off = 1; off <= 2; off <<= 1) {
                float o1 = __shfl_xor_sync(0xffffffff, gm1, off);
                int   oi = __shfl_xor_sync(0xffffffff, gi1, off);
                float o2 = __shfl_xor_sync(0xffffffff, gm2, off);
                if (o1 < gm1 || (o1 == gm1 && oi < gi1)) {
                    gm2 = fminf(gm1, o2); gm1 = o1; gi1 = oi;
                } else {
                    gm2 = fminf(gm2, o1);
                }
            }

            int winner = gi1;
            if (gm2 - gm1 < TAU) {
                const float th = gm1 + TAU;
                float ev = FLT_BIG; int ei = 0x7fffffff;
                const float* xr = x + ((size_t)(qbase + qrow) * MQ + m) * CQ;
                if (v2 < th) {
                    for (int np = 0; np < 16; np++) {
                        int nn[4] = { np*16 + r2, np*16 + r2 + 1,
                                      np*16 + 8 + r2, np*16 + 8 + r2 + 1 };
                        #pragma unroll
                        for (int j = 0; j < 4; j++) {
                            float d = exact_dist(xr, gcb + nn[j] * CQ, s_c2[nn[j]]);
                            if (d < ev || (d == ev && nn[j] < ei)) { ev = d; ei = nn[j]; }
                        }
                    }
                } else if (v1 < th) {
                    ev = exact_dist(xr, gcb + i1 * CQ, s_c2[i1]);
                    ei = i1;
                }
                #pragma unroll
                for (int off = 1; off <= 2; off <<= 1) {
                    float oe = __shfl_xor_sync(quadmask, ev, off);
                    int   oi = __shfl_xor_sync(quadmask, ei, off);
                    if (oe < ev || (oe == ev && oi < ei)) { ev = oe; ei = oi; }
                }
                winner = ei;
            }
            if ((lane & 3) == 0) s_win[qrow] = winner;
        }
    }
    __syncwarp();   // each warp reads only the s_win rows it wrote

    // ---- output: warp copies its 32 query rows ----
    #pragma unroll
    for (int i = 0; i < 32; i++) {
        int q = (i < 16) ? (wid * 16 + i) : (128 + wid * 16 + (i - 16));
        int n = s_win[q];
        size_t orow = ((size_t)(qbase + q) * MQ + m) * CQ;
        const float2* src = (const float2*)(gcb + (size_t)n * CQ);
        ((float2*)(out_codes + orow))[lane] = src[lane];
        if (lane == 0 && out_idx)
            out_idx[(size_t)(qbase + q) * MQ + m] = (float)n;
    }
}

extern "C" void kernel_launch(void* const* d_in, const int* in_sizes, int n_in,
                              void* d_out, int out_size) {
    const float* x  = (const float*)d_in[0];
    const float* cb = (const float*)d_in[1];
    if (n_in >= 2 && in_sizes[0] == MQ * NQ * CQ) {
        const float* tmp = x; x = cb; cb = tmp;
    }

    float* out_codes = (float*)d_out;
    float* out_idx   = nullptr;
    const long long codes_elems = (long long)BQ * MQ * CQ;   // 8388608
    if ((long long)out_size >= codes_elems + (long long)BQ * MQ)
        out_idx = out_codes + codes_elems;

    cudaFuncSetAttribute(fq_mma_kernel, cudaFuncAttributeMaxDynamicSharedMemorySize,
                         SM_TOTAL);
    dim3 grid(BQ / QT, MQ);   // 32 x 16 = 512 CTAs
    fq_mma_kernel<<<grid, NTHREADS, SM_TOTAL>>>(x, cb, out_codes, out_idx);
}